// round 11
// baseline (speedup 1.0000x reference)
#include <cuda_runtime.h>
#include <cuda_bf16.h>
#include <cstdint>

// Problem shapes
#define TOK   1024
#define HDIM  1024
#define FDIM  3584
#define NEXP  8

// Tiling: 64-row tiles
#define BMR 64
#define BK  32
#define MAXROWS  2560
#define MAXTILES 40

// ---------------- device scratch ----------------
__device__ __nv_bfloat16 g_xh[(size_t)TOK * HDIM];      // x hi plane
__device__ __nv_bfloat16 g_xl[(size_t)TOK * HDIM];      // x lo plane
__device__ __nv_bfloat16 g_ah[(size_t)MAXROWS * FDIM];  // act hi plane
__device__ __nv_bfloat16 g_al[(size_t)MAXROWS * FDIM];  // act lo plane
__device__ int    g_ptok[MAXROWS];
__device__ float  g_pw[MAXROWS];
__device__ int    g_tile_expert[MAXTILES];
__device__ int    g_nRowTiles;
__device__ int2   g_topi[TOK];
__device__ float2 g_topw[TOK];

// 64B-row swizzle: XOR bits[5:4] with bits[8:7] -> conflict-free ldmatrix
#define SWZ64(o) ((o) ^ (((o) >> 3) & 0x30))

__device__ __forceinline__ void ldmx4(uint32_t* r, uint32_t a) {
    asm volatile("ldmatrix.sync.aligned.m8n8.x4.shared.b16 {%0,%1,%2,%3}, [%4];"
                 : "=r"(r[0]), "=r"(r[1]), "=r"(r[2]), "=r"(r[3]) : "r"(a));
}
__device__ __forceinline__ void mma_bf16(float* d, const uint32_t* a, const uint32_t* b) {
    asm volatile("mma.sync.aligned.m16n8k16.row.col.f32.bf16.bf16.f32 "
                 "{%0,%1,%2,%3}, {%4,%5,%6,%7}, {%8,%9}, {%0,%1,%2,%3};"
                 : "+f"(d[0]), "+f"(d[1]), "+f"(d[2]), "+f"(d[3])
                 : "r"(a[0]), "r"(a[1]), "r"(a[2]), "r"(a[3]), "r"(b[0]), "r"(b[1]));
}
__device__ __forceinline__ void cpa16(uint32_t dst, const void* src) {
    asm volatile("cp.async.cg.shared.global [%0], [%1], 16;" :: "r"(dst), "l"(src));
}
#define CP_COMMIT() asm volatile("cp.async.commit_group;" ::: "memory")
#define CP_WAIT1()  asm volatile("cp.async.wait_group 1;" ::: "memory")

// fp32x4 -> bf16 hi/lo planes (packed as 2x uint2)
__device__ __forceinline__ void split4(float4 v, uint2& hp, uint2& lp) {
    __nv_bfloat16 h0 = __float2bfloat16_rn(v.x), h1 = __float2bfloat16_rn(v.y);
    __nv_bfloat16 h2 = __float2bfloat16_rn(v.z), h3 = __float2bfloat16_rn(v.w);
    __nv_bfloat16 l0 = __float2bfloat16_rn(v.x - __bfloat162float(h0));
    __nv_bfloat16 l1 = __float2bfloat16_rn(v.y - __bfloat162float(h1));
    __nv_bfloat16 l2 = __float2bfloat16_rn(v.z - __bfloat162float(h2));
    __nv_bfloat16 l3 = __float2bfloat16_rn(v.w - __bfloat162float(h3));
    hp.x = (uint32_t)__bfloat16_as_ushort(h0) | ((uint32_t)__bfloat16_as_ushort(h1) << 16);
    hp.y = (uint32_t)__bfloat16_as_ushort(h2) | ((uint32_t)__bfloat16_as_ushort(h3) << 16);
    lp.x = (uint32_t)__bfloat16_as_ushort(l0) | ((uint32_t)__bfloat16_as_ushort(l1) << 16);
    lp.y = (uint32_t)__bfloat16_as_ushort(l2) | ((uint32_t)__bfloat16_as_ushort(l3) << 16);
}
__device__ __forceinline__ void store_hl2(__nv_bfloat16* ph, __nv_bfloat16* pl,
                                          float v0, float v1) {
    __nv_bfloat16 h0 = __float2bfloat16_rn(v0), h1 = __float2bfloat16_rn(v1);
    __nv_bfloat16 l0 = __float2bfloat16_rn(v0 - __bfloat162float(h0));
    __nv_bfloat16 l1 = __float2bfloat16_rn(v1 - __bfloat162float(h1));
    *(uint32_t*)ph = (uint32_t)__bfloat16_as_ushort(h0) | ((uint32_t)__bfloat16_as_ushort(h1) << 16);
    *(uint32_t*)pl = (uint32_t)__bfloat16_as_ushort(l0) | ((uint32_t)__bfloat16_as_ushort(l1) << 16);
}
__device__ __forceinline__ float silumul(float h1, float h3) {
    return (h1 / (1.f + __expf(-h1))) * h3;
}

// ---------------- router (also writes x hi/lo planes) ----------------
__global__ void router_kernel(const float* __restrict__ x,
                              const float* __restrict__ gw,
                              float* __restrict__ out,
                              float* __restrict__ logits) {
    const int t = blockIdx.x;
    const int tid = threadIdx.x;
    const float* xr = x + (size_t)t * HDIM;

    float acc[NEXP];
#pragma unroll
    for (int e = 0; e < NEXP; e++) acc[e] = 0.f;
    for (int h = tid; h < HDIM; h += 128) {
        float xv = xr[h];
        __nv_bfloat16 hb = __float2bfloat16_rn(xv);
        g_xh[(size_t)t * HDIM + h] = hb;
        g_xl[(size_t)t * HDIM + h] = __float2bfloat16_rn(xv - __bfloat162float(hb));
#pragma unroll
        for (int e = 0; e < NEXP; e++) acc[e] += xv * gw[e * HDIM + h];
    }
    __shared__ float red[NEXP][128];
#pragma unroll
    for (int e = 0; e < NEXP; e++) red[e][tid] = acc[e];
    __syncthreads();
    for (int s = 64; s > 0; s >>= 1) {
        if (tid < s) {
#pragma unroll
            for (int e = 0; e < NEXP; e++) red[e][tid] += red[e][tid + s];
        }
        __syncthreads();
    }
    float* orow = out + (size_t)t * HDIM;
    for (int h = tid; h < HDIM; h += 128) orow[h] = 0.f;

    if (tid == 0) {
        float lg[NEXP];
        float mx = -1e30f;
#pragma unroll
        for (int e = 0; e < NEXP; e++) {
            lg[e] = red[e][0];
            logits[t * NEXP + e] = lg[e];
            mx = fmaxf(mx, lg[e]);
        }
        float pe[NEXP];
#pragma unroll
        for (int e = 0; e < NEXP; e++) pe[e] = expf(lg[e] - mx);
        int i1 = 0;
#pragma unroll
        for (int e = 1; e < NEXP; e++) if (pe[e] > pe[i1]) i1 = e;
        int i2 = (i1 == 0) ? 1 : 0;
#pragma unroll
        for (int e = 0; e < NEXP; e++) if (e != i2 && e != i1 && pe[e] > pe[i2]) i2 = e;
        float p1 = pe[i1], p2 = pe[i2];
        float inv = 1.f / (p1 + p2);
        g_topi[t] = make_int2(i1, i2);
        g_topw[t] = make_float2(p1 * inv, p2 * inv);
    }
}

// ---------------- token lists: warp-per-expert ballot compaction ----------------
__global__ void build_lists() {
    const int tid = threadIdx.x, wid = tid >> 5, lane = tid & 31;
    __shared__ int2 stop[TOK];
    __shared__ float2 stw[TOK];
    __shared__ int cnt[NEXP], off[NEXP];

    for (int t = tid; t < TOK; t += 256) { stop[t] = g_topi[t]; stw[t] = g_topw[t]; }
    __syncthreads();

    // count (warp wid = expert wid)
    {
        int c = 0;
        for (int t0 = 0; t0 < TOK; t0 += 32) {
            int2 ti = stop[t0 + lane];
            unsigned m = __ballot_sync(0xffffffffu, ti.x == wid || ti.y == wid);
            c += __popc(m);
        }
        if (lane == 0) cnt[wid] = c;
    }
    __syncthreads();
    if (tid == 0) {
        int o = 0;
        for (int e = 0; e < NEXP; e++) {
            off[e] = o;
            int pe = (cnt[e] + BMR - 1) & ~(BMR - 1);
            for (int tt = o / BMR; tt < (o + pe) / BMR; tt++) g_tile_expert[tt] = e;
            o += pe;
        }
        g_nRowTiles = o / BMR;
    }
    __syncthreads();

    // fill (ordered compaction via ballot prefix)
    {
        const int e = wid;
        int pos = off[e];
        for (int t0 = 0; t0 < TOK; t0 += 32) {
            const int t = t0 + lane;
            int2 ti = stop[t];
            const bool m1 = (ti.x == e);
            const bool m  = m1 || (ti.y == e);
            unsigned mask = __ballot_sync(0xffffffffu, m);
            int idx = pos + __popc(mask & ((1u << lane) - 1u));
            if (m) { g_ptok[idx] = t; g_pw[idx] = m1 ? stw[t].x : stw[t].y; }
            pos += __popc(mask);
        }
        const int end = off[e] + ((cnt[e] + BMR - 1) & ~(BMR - 1));
        for (int p = pos + lane; p < end; p += 32) { g_ptok[p] = 0; g_pw[p] = 0.f; }
    }
}

// ================= fused w1/w3 kernel: 64x64 tiles, 128 threads (R10) =================
#define A_BASE  1024
#define A_ST    8192
#define B_BASE1 (A_BASE + 3 * A_ST)      // 25600
#define B_ST1   16384
#define SM13    (B_BASE1 + 2 * B_ST1)    // 58368
#define NC1     (HDIM / BK)              // 32

__global__ void __launch_bounds__(128, 3)
moe_gemm13(const float* __restrict__ w1,
           const float* __restrict__ w3) {
    const int rt = blockIdx.y;
    if (rt >= g_nRowTiles) return;
    extern __shared__ char smem[];
    const uint32_t sb0 = (uint32_t)__cvta_generic_to_shared(smem);
    const int tid = threadIdx.x, wid = tid >> 5, lane = tid & 31;
    const int wm = wid & 1, wn = wid >> 1;
    const int e  = g_tile_expert[rt];
    const int n0 = blockIdx.x * 64;
    const int r0 = rt * BMR;

    int* s_tok = (int*)smem;
    if (tid < BMR) s_tok[tid] = g_ptok[r0 + tid];
    __syncthreads();

    const float* w1e = w1 + (size_t)e * FDIM * HDIM;
    const float* w3e = w3 + (size_t)e * FDIM * HDIM;

    const int arow = tid >> 1;
    const int aseg = (tid & 1) * 2;
    const __nv_bfloat16* axh = g_xh + (size_t)s_tok[arow] * HDIM + aseg * 8;
    const __nv_bfloat16* axl = g_xl + (size_t)s_tok[arow] * HDIM + aseg * 8;
    const uint32_t ad0 = SWZ64((uint32_t)(arow * 64 + aseg * 16));
    const uint32_t ad1 = SWZ64((uint32_t)(arow * 64 + aseg * 16 + 16));

    const int brow = tid >> 1, bcolf = (tid & 1) * 16;
    const float* b1p = w1e + (size_t)(n0 + brow) * HDIM + bcolf;
    const float* b3p = w3e + (size_t)(n0 + brow) * HDIM + bcolf;
    uint32_t boff[4];
#pragma unroll
    for (int j = 0; j < 4; j++) boff[j] = SWZ64((uint32_t)(brow * 64 + (bcolf + j * 4) * 2));

    float4 b1R[4], b3R[4];

#pragma unroll
    for (int p = 0; p < 2; p++) {
        uint32_t st = sb0 + A_BASE + p * A_ST;
        const int k0 = p * BK;
        cpa16(st + ad0, axh + k0);
        cpa16(st + ad1, axh + k0 + 8);
        cpa16(st + 4096 + ad0, axl + k0);
        cpa16(st + 4096 + ad1, axl + k0 + 8);
        CP_COMMIT();
    }
    {
#pragma unroll
        for (int j = 0; j < 4; j++) { b1R[j] = *(const float4*)(b1p + j * 4); b3R[j] = *(const float4*)(b3p + j * 4); }
        char* stc = smem + B_BASE1;
        uint2 hp, lp;
#pragma unroll
        for (int j = 0; j < 4; j++) {
            split4(b1R[j], hp, lp); *(uint2*)(stc + boff[j]) = hp;         *(uint2*)(stc + 4096 + boff[j]) = lp;
            split4(b3R[j], hp, lp); *(uint2*)(stc + 8192 + boff[j]) = hp;  *(uint2*)(stc + 12288 + boff[j]) = lp;
        }
    }

    float a1[2][4][4], a3[2][4][4];
#pragma unroll
    for (int m = 0; m < 2; m++)
#pragma unroll
        for (int n = 0; n < 4; n++)
#pragma unroll
            for (int q = 0; q < 4; q++) { a1[m][n][q] = 0.f; a3[m][n][q] = 0.f; }

    for (int c = 0; c < NC1; c++) {
        CP_WAIT1();
        __syncthreads();

        const int cpf = c + 2;
        if (cpf < NC1) {
            uint32_t st = sb0 + A_BASE + (cpf % 3) * A_ST;
            const int k0 = cpf * BK;
            cpa16(st + ad0, axh + k0);
            cpa16(st + ad1, axh + k0 + 8);
            cpa16(st + 4096 + ad0, axl + k0);
            cpa16(st + 4096 + ad1, axl + k0 + 8);
        }
        CP_COMMIT();

        if (c + 1 < NC1) {
            const int kn = (c + 1) * BK;
#pragma unroll
            for (int j = 0; j < 4; j++) { b1R[j] = *(const float4*)(b1p + kn + j * 4); b3R[j] = *(const float4*)(b3p + kn + j * 4); }
        }

        const uint32_t sa = sb0 + A_BASE + (c % 3) * A_ST;
        const uint32_t sbb = sb0 + B_BASE1 + (c & 1) * B_ST1;
#pragma unroll
        for (int s = 0; s < 2; s++) {
            const int ks = s * 16;
            uint32_t ah[2][4], al[2][4];
#pragma unroll
            for (int mt = 0; mt < 2; mt++) {
                uint32_t ro = SWZ64((uint32_t)((wm * 32 + mt * 16 + (lane & 15)) * 64 + (ks + (lane >> 4) * 8) * 2));
                ldmx4(ah[mt], sa + ro);
                ldmx4(al[mt], sa + 4096 + ro);
            }
            uint32_t b1h[2][4], b1l[2][4], b3h[2][4], b3l[2][4];
#pragma unroll
            for (int np = 0; np < 2; np++) {
                uint32_t ro = SWZ64((uint32_t)((wn * 32 + np * 16 + ((lane >> 4) & 1) * 8 + (lane & 7)) * 64 +
                                               (ks + ((lane >> 3) & 1) * 8) * 2));
                ldmx4(b1h[np], sbb + ro);
                ldmx4(b1l[np], sbb + 4096 + ro);
                ldmx4(b3h[np], sbb + 8192 + ro);
                ldmx4(b3l[np], sbb + 12288 + ro);
            }
#pragma unroll
            for (int mt = 0; mt < 2; mt++)
#pragma unroll
                for (int np = 0; np < 2; np++)
#pragma unroll
                    for (int h = 0; h < 2; h++) {
                        const int nt2 = np * 2 + h;
                        mma_bf16(a1[mt][nt2], ah[mt], &b1h[np][h * 2]);
                        mma_bf16(a1[mt][nt2], ah[mt], &b1l[np][h * 2]);
                        mma_bf16(a1[mt][nt2], al[mt], &b1h[np][h * 2]);
                        mma_bf16(a3[mt][nt2], ah[mt], &b3h[np][h * 2]);
                        mma_bf16(a3[mt][nt2], ah[mt], &b3l[np][h * 2]);
                        mma_bf16(a3[mt][nt2], al[mt], &b3h[np][h * 2]);
                    }
        }
        if (c + 1 < NC1) {
            char* stc = smem + B_BASE1 + ((c + 1) & 1) * B_ST1;
            uint2 hp, lp;
#pragma unroll
            for (int j = 0; j < 4; j++) {
                split4(b1R[j], hp, lp); *(uint2*)(stc + boff[j]) = hp;         *(uint2*)(stc + 4096 + boff[j]) = lp;
                split4(b3R[j], hp, lp); *(uint2*)(stc + 8192 + boff[j]) = hp;  *(uint2*)(stc + 12288 + boff[j]) = lp;
            }
        }
    }

#pragma unroll
    for (int mt = 0; mt < 2; mt++)
#pragma unroll
        for (int nt2 = 0; nt2 < 4; nt2++) {
            const int row = r0 + wm * 32 + mt * 16 + (lane >> 2);
            const int col = n0 + wn * 32 + nt2 * 8 + 2 * (lane & 3);
            store_hl2(g_ah + (size_t)row * FDIM + col, g_al + (size_t)row * FDIM + col,
                      silumul(a1[mt][nt2][0], a3[mt][nt2][0]),
                      silumul(a1[mt][nt2][1], a3[mt][nt2][1]));
            store_hl2(g_ah + (size_t)(row + 8) * FDIM + col, g_al + (size_t)(row + 8) * FDIM + col,
                      silumul(a1[mt][nt2][2], a3[mt][nt2][2]),
                      silumul(a1[mt][nt2][3], a3[mt][nt2][3]));
        }
}

// ================= w2 kernel: 64(M) x 128(N) tiles, 128 threads, 4 warps 32x64 =================
// A: 3-stage ring 8KB/stage (hi 0, lo 4K); B: 2-stage 16KB/stage (hi 0, lo 8K; 128 rows x 64B)
#define B_BASE2 (A_BASE + 3 * A_ST)      // 25600
#define B_ST2   16384
#define SM2     (B_BASE2 + 2 * B_ST2)    // 58368
#define NC2     (FDIM / BK)              // 112

__global__ void __launch_bounds__(128, 3)
moe_gemm2(const float* __restrict__ w2, float* __restrict__ out) {
    const int rt = blockIdx.y;
    if (rt >= g_nRowTiles) return;
    extern __shared__ char smem[];
    const uint32_t sb0 = (uint32_t)__cvta_generic_to_shared(smem);
    const int tid = threadIdx.x, wid = tid >> 5, lane = tid & 31;
    const int wm = wid & 1, wn = wid >> 1;
    const int e  = g_tile_expert[rt];
    const int n0 = blockIdx.x * 128;
    const int r0 = rt * BMR;

    int*   s_tok = (int*)smem;
    float* s_w   = (float*)(smem + 256);
    if (tid < BMR) { s_tok[tid] = g_ptok[r0 + tid]; s_w[tid] = g_pw[r0 + tid]; }
    __syncthreads();

    const float* w2e = w2 + (size_t)e * HDIM * FDIM;

    // A cp.async role (64 rows, 2 threads/row)
    const int arow = tid >> 1;
    const int aseg = (tid & 1) * 2;
    const __nv_bfloat16* aph = g_ah + (size_t)(r0 + arow) * FDIM + aseg * 8;
    const __nv_bfloat16* apl = g_al + (size_t)(r0 + arow) * FDIM + aseg * 8;
    const uint32_t ad0 = SWZ64((uint32_t)(arow * 64 + aseg * 16));
    const uint32_t ad1 = SWZ64((uint32_t)(arow * 64 + aseg * 16 + 16));

    // B staging role: 1 thread per row (128 rows), full 32-k row (128B fp32)
    const float* bp = w2e + (size_t)(n0 + tid) * FDIM;
    uint32_t boff[8];
#pragma unroll
    for (int j = 0; j < 8; j++) boff[j] = SWZ64((uint32_t)(tid * 64 + j * 8));

    float4 bR[8];

    // prologue: A chunks 0,1 -> stages 0,1; B chunk 0 staged
#pragma unroll
    for (int p = 0; p < 2; p++) {
        uint32_t st = sb0 + A_BASE + p * A_ST;
        const int k0 = p * BK;
        cpa16(st + ad0, aph + k0);
        cpa16(st + ad1, aph + k0 + 8);
        cpa16(st + 4096 + ad0, apl + k0);
        cpa16(st + 4096 + ad1, apl + k0 + 8);
        CP_COMMIT();
    }
    {
#pragma unroll
        for (int j = 0; j < 8; j++) bR[j] = *(const float4*)(bp + j * 4);
        char* stc = smem + B_BASE2;
        uint2 hp, lp;
#pragma unroll
        for (int j = 0; j < 8; j++) { split4(bR[j], hp, lp); *(uint2*)(stc + boff[j]) = hp; *(uint2*)(stc + 8192 + boff[j]) = lp; }
    }

    float acc[2][8][4];
#pragma unroll
    for (int m = 0; m < 2; m++)
#pragma unroll
        for (int n = 0; n < 8; n++)
#pragma unroll
            for (int q = 0; q < 4; q++) acc[m][n][q] = 0.f;

    for (int c = 0; c < NC2; c++) {
        CP_WAIT1();
        __syncthreads();

        const int cpf = c + 2;
        if (cpf < NC2) {
            uint32_t st = sb0 + A_BASE + (cpf % 3) * A_ST;
            const int k0 = cpf * BK;
            cpa16(st + ad0, aph + k0);
            cpa16(st + ad1, aph + k0 + 8);
            cpa16(st + 4096 + ad0, apl + k0);
            cpa16(st + 4096 + ad1, apl + k0 + 8);
        }
        CP_COMMIT();

        if (c + 1 < NC2) {
            const int kn = (c + 1) * BK;
#pragma unroll
            for (int j = 0; j < 8; j++) bR[j] = *(const float4*)(bp + kn + j * 4);
        }

        const uint32_t sa = sb0 + A_BASE + (c % 3) * A_ST;
        const uint32_t sbb = sb0 + B_BASE2 + (c & 1) * B_ST2;
#pragma unroll
        for (int s = 0; s < 2; s++) {
            const int ks = s * 16;
            uint32_t ah[2][4], al[2][4];
#pragma unroll
            for (int mt = 0; mt < 2; mt++) {
                uint32_t ro = SWZ64((uint32_t)((wm * 32 + mt * 16 + (lane & 15)) * 64 + (ks + (lane >> 4) * 8) * 2));
                ldmx4(ah[mt], sa + ro);
                ldmx4(al[mt], sa + 4096 + ro);
            }
#pragma unroll
            for (int np = 0; np < 4; np++) {
                uint32_t bh[4], bl[4];
                uint32_t ro = SWZ64((uint32_t)((wn * 64 + np * 16 + ((lane >> 4) & 1) * 8 + (lane & 7)) * 64 +
                                               (ks + ((lane >> 3) & 1) * 8) * 2));
                ldmx4(bh, sbb + ro);
                ldmx4(bl, sbb + 8192 + ro);
#pragma unroll
                for (int mt = 0; mt < 2; mt++)
#pragma unroll
                    for (int h = 0; h < 2; h++) {
                        const int nt2 = np * 2 + h;
                        mma_bf16(acc[mt][nt2], ah[mt], &bh[h * 2]);
                        mma_bf16(acc[mt][nt2], ah[mt], &bl[h * 2]);
                        mma_bf16(acc[mt][nt2], al[mt], &bh[h * 2]);
                    }
            }
        }
        if (c + 1 < NC2) {
            char* stc = smem + B_BASE2 + ((c + 1) & 1) * B_ST2;
            uint2 hp, lp;
#pragma unroll
            for (int j = 0; j < 8; j++) { split4(bR[j], hp, lp); *(uint2*)(stc + boff[j]) = hp; *(uint2*)(stc + 8192 + boff[j]) = lp; }
        }
    }

    // epilogue: weighted atomic combine
#pragma unroll
    for (int mt = 0; mt < 2; mt++) {
        const int lr0 = wm * 32 + mt * 16 + (lane >> 2);
        const int tok0 = s_tok[lr0];     const float wt0 = s_w[lr0];
        const int tok1 = s_tok[lr0 + 8]; const float wt1 = s_w[lr0 + 8];
#pragma unroll
        for (int nt2 = 0; nt2 < 8; nt2++) {
            const int col = n0 + wn * 64 + nt2 * 8 + 2 * (lane & 3);
            float* o0 = out + (size_t)tok0 * HDIM + col;
            float* o1 = out + (size_t)tok1 * HDIM + col;
            atomicAdd(o0,     wt0 * acc[mt][nt2][0]);
            atomicAdd(o0 + 1, wt0 * acc[mt][nt2][1]);
            atomicAdd(o1,     wt1 * acc[mt][nt2][2]);
            atomicAdd(o1 + 1, wt1 * acc[mt][nt2][3]);
        }
    }
}

// ---------------- launch ----------------
extern "C" void kernel_launch(void* const* d_in, const int* in_sizes, int n_in,
                              void* d_out, int out_size) {
    const float* x  = (const float*)d_in[0];
    const float* gw = (const float*)d_in[1];
    const float* w1 = (const float*)d_in[2];
    const float* w2 = (const float*)d_in[3];
    const float* w3 = (const float*)d_in[4];

    float* out    = (float*)d_out;
    float* logits = out + (size_t)TOK * HDIM;

    cudaFuncSetAttribute(moe_gemm13, cudaFuncAttributeMaxDynamicSharedMemorySize, SM13);
    cudaFuncSetAttribute(moe_gemm2,  cudaFuncAttributeMaxDynamicSharedMemorySize, SM2);

    router_kernel<<<TOK, 128>>>(x, gw, out, logits);
    build_lists<<<1, 256>>>();
    moe_gemm13<<<dim3(FDIM / 64, MAXTILES), 128, SM13>>>(w1, w3);
    moe_gemm2<<<dim3(HDIM / 128, MAXTILES), 128, SM2>>>(w2, out);
}

// round 12
// speedup vs baseline: 1.2514x; 1.2514x over previous
#include <cuda_runtime.h>
#include <cuda_bf16.h>
#include <cstdint>

// Problem shapes
#define TOK   1024
#define HDIM  1024
#define FDIM  3584
#define NEXP  8

// Tiling: 64-row tiles, 128-thread CTAs, 4 warps of 32x32 outputs
#define BMR 64
#define BK  32
#define MAXROWS  2560
#define MAXTILES 40

// ---------------- device scratch ----------------
__device__ __nv_bfloat16 g_xh[(size_t)TOK * HDIM];      // x hi plane
__device__ __nv_bfloat16 g_xl[(size_t)TOK * HDIM];      // x lo plane
__device__ __nv_bfloat16 g_ah[(size_t)MAXROWS * FDIM];  // act hi plane
__device__ __nv_bfloat16 g_al[(size_t)MAXROWS * FDIM];  // act lo plane
__device__ int    g_ptok[MAXROWS];
__device__ float  g_pw[MAXROWS];
__device__ int    g_tile_expert[MAXTILES];
__device__ int    g_nRowTiles;
__device__ int2   g_topi[TOK];
__device__ float2 g_topw[TOK];

// 64B-row swizzle: XOR bits[5:4] with bits[8:7] -> conflict-free ldmatrix
#define SWZ64(o) ((o) ^ (((o) >> 3) & 0x30))

__device__ __forceinline__ void ldmx4(uint32_t* r, uint32_t a) {
    asm volatile("ldmatrix.sync.aligned.m8n8.x4.shared.b16 {%0,%1,%2,%3}, [%4];"
                 : "=r"(r[0]), "=r"(r[1]), "=r"(r[2]), "=r"(r[3]) : "r"(a));
}
__device__ __forceinline__ void mma_bf16(float* d, const uint32_t* a, const uint32_t* b) {
    asm volatile("mma.sync.aligned.m16n8k16.row.col.f32.bf16.bf16.f32 "
                 "{%0,%1,%2,%3}, {%4,%5,%6,%7}, {%8,%9}, {%0,%1,%2,%3};"
                 : "+f"(d[0]), "+f"(d[1]), "+f"(d[2]), "+f"(d[3])
                 : "r"(a[0]), "r"(a[1]), "r"(a[2]), "r"(a[3]), "r"(b[0]), "r"(b[1]));
}
__device__ __forceinline__ void cpa16(uint32_t dst, const void* src) {
    asm volatile("cp.async.cg.shared.global [%0], [%1], 16;" :: "r"(dst), "l"(src));
}
#define CP_COMMIT() asm volatile("cp.async.commit_group;" ::: "memory")
#define CP_WAIT1()  asm volatile("cp.async.wait_group 1;" ::: "memory")

// fp32x4 -> bf16 hi/lo planes (packed as 2x uint2)
__device__ __forceinline__ void split4(float4 v, uint2& hp, uint2& lp) {
    __nv_bfloat16 h0 = __float2bfloat16_rn(v.x), h1 = __float2bfloat16_rn(v.y);
    __nv_bfloat16 h2 = __float2bfloat16_rn(v.z), h3 = __float2bfloat16_rn(v.w);
    __nv_bfloat16 l0 = __float2bfloat16_rn(v.x - __bfloat162float(h0));
    __nv_bfloat16 l1 = __float2bfloat16_rn(v.y - __bfloat162float(h1));
    __nv_bfloat16 l2 = __float2bfloat16_rn(v.z - __bfloat162float(h2));
    __nv_bfloat16 l3 = __float2bfloat16_rn(v.w - __bfloat162float(h3));
    hp.x = (uint32_t)__bfloat16_as_ushort(h0) | ((uint32_t)__bfloat16_as_ushort(h1) << 16);
    hp.y = (uint32_t)__bfloat16_as_ushort(h2) | ((uint32_t)__bfloat16_as_ushort(h3) << 16);
    lp.x = (uint32_t)__bfloat16_as_ushort(l0) | ((uint32_t)__bfloat16_as_ushort(l1) << 16);
    lp.y = (uint32_t)__bfloat16_as_ushort(l2) | ((uint32_t)__bfloat16_as_ushort(l3) << 16);
}
__device__ __forceinline__ void store_hl2(__nv_bfloat16* ph, __nv_bfloat16* pl,
                                          float v0, float v1) {
    __nv_bfloat16 h0 = __float2bfloat16_rn(v0), h1 = __float2bfloat16_rn(v1);
    __nv_bfloat16 l0 = __float2bfloat16_rn(v0 - __bfloat162float(h0));
    __nv_bfloat16 l1 = __float2bfloat16_rn(v1 - __bfloat162float(h1));
    *(uint32_t*)ph = (uint32_t)__bfloat16_as_ushort(h0) | ((uint32_t)__bfloat16_as_ushort(h1) << 16);
    *(uint32_t*)pl = (uint32_t)__bfloat16_as_ushort(l0) | ((uint32_t)__bfloat16_as_ushort(l1) << 16);
}
__device__ __forceinline__ float silumul(float h1, float h3) {
    return (h1 / (1.f + __expf(-h1))) * h3;
}

// ---------------- router (also writes x hi/lo planes) ----------------
__global__ void router_kernel(const float* __restrict__ x,
                              const float* __restrict__ gw,
                              float* __restrict__ out,
                              float* __restrict__ logits) {
    const int t = blockIdx.x;
    const int tid = threadIdx.x;
    const float* xr = x + (size_t)t * HDIM;

    float acc[NEXP];
#pragma unroll
    for (int e = 0; e < NEXP; e++) acc[e] = 0.f;
    for (int h = tid; h < HDIM; h += 128) {
        float xv = xr[h];
        __nv_bfloat16 hb = __float2bfloat16_rn(xv);
        g_xh[(size_t)t * HDIM + h] = hb;
        g_xl[(size_t)t * HDIM + h] = __float2bfloat16_rn(xv - __bfloat162float(hb));
#pragma unroll
        for (int e = 0; e < NEXP; e++) acc[e] += xv * gw[e * HDIM + h];
    }
    __shared__ float red[NEXP][128];
#pragma unroll
    for (int e = 0; e < NEXP; e++) red[e][tid] = acc[e];
    __syncthreads();
    for (int s = 64; s > 0; s >>= 1) {
        if (tid < s) {
#pragma unroll
            for (int e = 0; e < NEXP; e++) red[e][tid] += red[e][tid + s];
        }
        __syncthreads();
    }
    float* orow = out + (size_t)t * HDIM;
    for (int h = tid; h < HDIM; h += 128) orow[h] = 0.f;

    if (tid == 0) {
        float lg[NEXP];
        float mx = -1e30f;
#pragma unroll
        for (int e = 0; e < NEXP; e++) {
            lg[e] = red[e][0];
            logits[t * NEXP + e] = lg[e];
            mx = fmaxf(mx, lg[e]);
        }
        float pe[NEXP];
#pragma unroll
        for (int e = 0; e < NEXP; e++) pe[e] = expf(lg[e] - mx);
        int i1 = 0;
#pragma unroll
        for (int e = 1; e < NEXP; e++) if (pe[e] > pe[i1]) i1 = e;
        int i2 = (i1 == 0) ? 1 : 0;
#pragma unroll
        for (int e = 0; e < NEXP; e++) if (e != i2 && e != i1 && pe[e] > pe[i2]) i2 = e;
        float p1 = pe[i1], p2 = pe[i2];
        float inv = 1.f / (p1 + p2);
        g_topi[t] = make_int2(i1, i2);
        g_topw[t] = make_float2(p1 * inv, p2 * inv);
    }
}

// ---------------- token lists: warp-per-expert ballot compaction ----------------
__global__ void build_lists() {
    const int tid = threadIdx.x, wid = tid >> 5, lane = tid & 31;
    __shared__ int2 stop[TOK];
    __shared__ float2 stw[TOK];
    __shared__ int cnt[NEXP], off[NEXP];

    for (int t = tid; t < TOK; t += 256) { stop[t] = g_topi[t]; stw[t] = g_topw[t]; }
    __syncthreads();

    // count (warp wid = expert wid)
    {
        int c = 0;
        for (int t0 = 0; t0 < TOK; t0 += 32) {
            int2 ti = stop[t0 + lane];
            unsigned m = __ballot_sync(0xffffffffu, ti.x == wid || ti.y == wid);
            c += __popc(m);
        }
        if (lane == 0) cnt[wid] = c;
    }
    __syncthreads();
    if (tid == 0) {
        int o = 0;
        for (int e = 0; e < NEXP; e++) {
            off[e] = o;
            int pe = (cnt[e] + BMR - 1) & ~(BMR - 1);
            for (int tt = o / BMR; tt < (o + pe) / BMR; tt++) g_tile_expert[tt] = e;
            o += pe;
        }
        g_nRowTiles = o / BMR;
    }
    __syncthreads();

    // fill (ordered compaction via ballot prefix)
    {
        const int e = wid;
        int pos = off[e];
        for (int t0 = 0; t0 < TOK; t0 += 32) {
            const int t = t0 + lane;
            int2 ti = stop[t];
            const bool m1 = (ti.x == e);
            const bool m  = m1 || (ti.y == e);
            unsigned mask = __ballot_sync(0xffffffffu, m);
            int idx = pos + __popc(mask & ((1u << lane) - 1u));
            if (m) { g_ptok[idx] = t; g_pw[idx] = m1 ? stw[t].x : stw[t].y; }
            pos += __popc(mask);
        }
        const int end = off[e] + ((cnt[e] + BMR - 1) & ~(BMR - 1));
        for (int p = pos + lane; p < end; p += 32) { g_ptok[p] = 0; g_pw[p] = 0.f; }
    }
}

// ================= fused w1/w3 kernel: 64x64 tiles, 128 threads =================
// A: 3-stage ring, 8KB/stage (hi @0, lo @4K), SWZ64 rows of 64B
// B: 2-stage, 16KB/stage (b1hi 0, b1lo 4K, b3hi 8K, b3lo 12K)
#define A_BASE  1024
#define A_ST    8192
#define B_BASE1 (A_BASE + 3 * A_ST)      // 25600
#define B_ST1   16384
#define SM13    (B_BASE1 + 2 * B_ST1)    // 58368
#define NC1     (HDIM / BK)              // 32

__global__ void __launch_bounds__(128, 3)
moe_gemm13(const float* __restrict__ w1,
           const float* __restrict__ w3) {
    const int rt = blockIdx.y;
    if (rt >= g_nRowTiles) return;
    extern __shared__ char smem[];
    const uint32_t sb0 = (uint32_t)__cvta_generic_to_shared(smem);
    const int tid = threadIdx.x, wid = tid >> 5, lane = tid & 31;
    const int wm = wid & 1, wn = wid >> 1;
    const int e  = g_tile_expert[rt];
    const int n0 = blockIdx.x * 64;
    const int r0 = rt * BMR;

    int* s_tok = (int*)smem;
    if (tid < BMR) s_tok[tid] = g_ptok[r0 + tid];
    __syncthreads();

    const float* w1e = w1 + (size_t)e * FDIM * HDIM;
    const float* w3e = w3 + (size_t)e * FDIM * HDIM;

    // A cp.async role: row = tid>>1 (64 rows), seg = (tid&1)*2 (two 16B pieces)
    const int arow = tid >> 1;
    const int aseg = (tid & 1) * 2;
    const __nv_bfloat16* axh = g_xh + (size_t)s_tok[arow] * HDIM + aseg * 8;
    const __nv_bfloat16* axl = g_xl + (size_t)s_tok[arow] * HDIM + aseg * 8;
    const uint32_t ad0 = SWZ64((uint32_t)(arow * 64 + aseg * 16));
    const uint32_t ad1 = SWZ64((uint32_t)(arow * 64 + aseg * 16 + 16));

    // B staging role: row = tid>>1 (64 rows), 16 floats each
    const int brow = tid >> 1, bcolf = (tid & 1) * 16;
    const float* b1p = w1e + (size_t)(n0 + brow) * HDIM + bcolf;
    const float* b3p = w3e + (size_t)(n0 + brow) * HDIM + bcolf;
    uint32_t boff[4];
#pragma unroll
    for (int j = 0; j < 4; j++) boff[j] = SWZ64((uint32_t)(brow * 64 + (bcolf + j * 4) * 2));

    float4 b1R[4], b3R[4];

    // prologue: A chunks 0,1 -> stages 0,1; B chunk 0 staged into buf 0
#pragma unroll
    for (int p = 0; p < 2; p++) {
        uint32_t st = sb0 + A_BASE + p * A_ST;
        const int k0 = p * BK;
        cpa16(st + ad0, axh + k0);
        cpa16(st + ad1, axh + k0 + 8);
        cpa16(st + 4096 + ad0, axl + k0);
        cpa16(st + 4096 + ad1, axl + k0 + 8);
        CP_COMMIT();
    }
    {
#pragma unroll
        for (int j = 0; j < 4; j++) { b1R[j] = *(const float4*)(b1p + j * 4); b3R[j] = *(const float4*)(b3p + j * 4); }
        char* stc = smem + B_BASE1;
        uint2 hp, lp;
#pragma unroll
        for (int j = 0; j < 4; j++) {
            split4(b1R[j], hp, lp); *(uint2*)(stc + boff[j]) = hp;         *(uint2*)(stc + 4096 + boff[j]) = lp;
            split4(b3R[j], hp, lp); *(uint2*)(stc + 8192 + boff[j]) = hp;  *(uint2*)(stc + 12288 + boff[j]) = lp;
        }
    }

    float a1[2][4][4], a3[2][4][4];
#pragma unroll
    for (int m = 0; m < 2; m++)
#pragma unroll
        for (int n = 0; n < 4; n++)
#pragma unroll
            for (int q = 0; q < 4; q++) { a1[m][n][q] = 0.f; a3[m][n][q] = 0.f; }

    for (int c = 0; c < NC1; c++) {
        CP_WAIT1();           // A chunk c landed (c+1 may be in flight)
        __syncthreads();      // all warps done with chunk c-1 smem reads

        // issue A chunk c+2 into stage (c+2)%3 (its last readers finished at c-1)
        const int cpf = c + 2;
        if (cpf < NC1) {
            uint32_t st = sb0 + A_BASE + (cpf % 3) * A_ST;
            const int k0 = cpf * BK;
            cpa16(st + ad0, axh + k0);
            cpa16(st + ad1, axh + k0 + 8);
            cpa16(st + 4096 + ad0, axl + k0);
            cpa16(st + 4096 + ad1, axl + k0 + 8);
        }
        CP_COMMIT();

        if (c + 1 < NC1) {
            const int kn = (c + 1) * BK;
#pragma unroll
            for (int j = 0; j < 4; j++) { b1R[j] = *(const float4*)(b1p + kn + j * 4); b3R[j] = *(const float4*)(b3p + kn + j * 4); }
        }

        const uint32_t sa = sb0 + A_BASE + (c % 3) * A_ST;
        const uint32_t sbb = sb0 + B_BASE1 + (c & 1) * B_ST1;
#pragma unroll
        for (int s = 0; s < 2; s++) {
            const int ks = s * 16;
            uint32_t ah[2][4], al[2][4];
#pragma unroll
            for (int mt = 0; mt < 2; mt++) {
                uint32_t ro = SWZ64((uint32_t)((wm * 32 + mt * 16 + (lane & 15)) * 64 + (ks + (lane >> 4) * 8) * 2));
                ldmx4(ah[mt], sa + ro);
                ldmx4(al[mt], sa + 4096 + ro);
            }
            uint32_t b1h[2][4], b1l[2][4], b3h[2][4], b3l[2][4];
#pragma unroll
            for (int np = 0; np < 2; np++) {
                uint32_t ro = SWZ64((uint32_t)((wn * 32 + np * 16 + ((lane >> 4) & 1) * 8 + (lane & 7)) * 64 +
                                               (ks + ((lane >> 3) & 1) * 8) * 2));
                ldmx4(b1h[np], sbb + ro);
                ldmx4(b1l[np], sbb + 4096 + ro);
                ldmx4(b3h[np], sbb + 8192 + ro);
                ldmx4(b3l[np], sbb + 12288 + ro);
            }
#pragma unroll
            for (int mt = 0; mt < 2; mt++)
#pragma unroll
                for (int np = 0; np < 2; np++)
#pragma unroll
                    for (int h = 0; h < 2; h++) {
                        const int nt2 = np * 2 + h;
                        mma_bf16(a1[mt][nt2], ah[mt], &b1h[np][h * 2]);
                        mma_bf16(a1[mt][nt2], ah[mt], &b1l[np][h * 2]);
                        mma_bf16(a1[mt][nt2], al[mt], &b1h[np][h * 2]);
                        mma_bf16(a3[mt][nt2], ah[mt], &b3h[np][h * 2]);
                        mma_bf16(a3[mt][nt2], ah[mt], &b3l[np][h * 2]);
                        mma_bf16(a3[mt][nt2], al[mt], &b3h[np][h * 2]);
                    }
        }
        if (c + 1 < NC1) {
            // write buf (c+1)&1: its readers (chunk c-1) finished before this iter's barrier
            char* stc = smem + B_BASE1 + ((c + 1) & 1) * B_ST1;
            uint2 hp, lp;
#pragma unroll
            for (int j = 0; j < 4; j++) {
                split4(b1R[j], hp, lp); *(uint2*)(stc + boff[j]) = hp;         *(uint2*)(stc + 4096 + boff[j]) = lp;
                split4(b3R[j], hp, lp); *(uint2*)(stc + 8192 + boff[j]) = hp;  *(uint2*)(stc + 12288 + boff[j]) = lp;
            }
        }
    }

    // epilogue: act = silu(h1)*h3 -> hi/lo planes
#pragma unroll
    for (int mt = 0; mt < 2; mt++)
#pragma unroll
        for (int nt2 = 0; nt2 < 4; nt2++) {
            const int row = r0 + wm * 32 + mt * 16 + (lane >> 2);
            const int col = n0 + wn * 32 + nt2 * 8 + 2 * (lane & 3);
            store_hl2(g_ah + (size_t)row * FDIM + col, g_al + (size_t)row * FDIM + col,
                      silumul(a1[mt][nt2][0], a3[mt][nt2][0]),
                      silumul(a1[mt][nt2][1], a3[mt][nt2][1]));
            store_hl2(g_ah + (size_t)(row + 8) * FDIM + col, g_al + (size_t)(row + 8) * FDIM + col,
                      silumul(a1[mt][nt2][2], a3[mt][nt2][2]),
                      silumul(a1[mt][nt2][3], a3[mt][nt2][3]));
        }
}

// ================= w2 kernel: 64x64 tiles, 128 threads =================
// A: 3-stage ring 8KB/stage; B: 2-stage 8KB/stage (bhi 0, blo 4K)
#define B_BASE2 (A_BASE + 3 * A_ST)      // 25600
#define B_ST2   8192
#define SM2     (B_BASE2 + 2 * B_ST2)    // 41984
#define NC2     (FDIM / BK)              // 112

__global__ void __launch_bounds__(128, 4)
moe_gemm2(const float* __restrict__ w2, float* __restrict__ out) {
    const int rt = blockIdx.y;
    if (rt >= g_nRowTiles) return;
    extern __shared__ char smem[];
    const uint32_t sb0 = (uint32_t)__cvta_generic_to_shared(smem);
    const int tid = threadIdx.x, wid = tid >> 5, lane = tid & 31;
    const int wm = wid & 1, wn = wid >> 1;
    const int e  = g_tile_expert[rt];
    const int n0 = blockIdx.x * 64;
    const int r0 = rt * BMR;

    int*   s_tok = (int*)smem;
    float* s_w   = (float*)(smem + 256);
    if (tid < BMR) { s_tok[tid] = g_ptok[r0 + tid]; s_w[tid] = g_pw[r0 + tid]; }
    __syncthreads();

    const float* w2e = w2 + (size_t)e * HDIM * FDIM;

    const int arow = tid >> 1;
    const int aseg = (tid & 1) * 2;
    const __nv_bfloat16* aph = g_ah + (size_t)(r0 + arow) * FDIM + aseg * 8;
    const __nv_bfloat16* apl = g_al + (size_t)(r0 + arow) * FDIM + aseg * 8;
    const uint32_t ad0 = SWZ64((uint32_t)(arow * 64 + aseg * 16));
    const uint32_t ad1 = SWZ64((uint32_t)(arow * 64 + aseg * 16 + 16));

    const int brow = tid >> 1, bcolf = (tid & 1) * 16;
    const float* bp = w2e + (size_t)(n0 + brow) * FDIM + bcolf;
    uint32_t boff[4];
#pragma unroll
    for (int j = 0; j < 4; j++) boff[j] = SWZ64((uint32_t)(brow * 64 + (bcolf + j * 4) * 2));

    float4 bR[4];

    // prologue
#pragma unroll
    for (int p = 0; p < 2; p++) {
        uint32_t st = sb0 + A_BASE + p * A_ST;
        const int k0 = p * BK;
        cpa16(st + ad0, aph + k0);
        cpa16(st + ad1, aph + k0 + 8);
        cpa16(st + 4096 + ad0, apl + k0);
        cpa16(st + 4096 + ad1, apl + k0 + 8);
        CP_COMMIT();
    }
    {
#pragma unroll
        for (int j = 0; j < 4; j++) bR[j] = *(const float4*)(bp + j * 4);
        char* stc = smem + B_BASE2;
        uint2 hp, lp;
#pragma unroll
        for (int j = 0; j < 4; j++) { split4(bR[j], hp, lp); *(uint2*)(stc + boff[j]) = hp; *(uint2*)(stc + 4096 + boff[j]) = lp; }
    }

    float acc[2][4][4];
#pragma unroll
    for (int m = 0; m < 2; m++)
#pragma unroll
        for (int n = 0; n < 4; n++)
#pragma unroll
            for (int q = 0; q < 4; q++) acc[m][n][q] = 0.f;

    for (int c = 0; c < NC2; c++) {
        CP_WAIT1();
        __syncthreads();

        const int cpf = c + 2;
        if (cpf < NC2) {
            uint32_t st = sb0 + A_BASE + (cpf % 3) * A_ST;
            const int k0 = cpf * BK;
            cpa16(st + ad0, aph + k0);
            cpa16(st + ad1, aph + k0 + 8);
            cpa16(st + 4096 + ad0, apl + k0);
            cpa16(st + 4096 + ad1, apl + k0 + 8);
        }
        CP_COMMIT();

        if (c + 1 < NC2) {
            const int kn = (c + 1) * BK;
#pragma unroll
            for (int j = 0; j < 4; j++) bR[j] = *(const float4*)(bp + kn + j * 4);
        }

        const uint32_t sa = sb0 + A_BASE + (c % 3) * A_ST;
        const uint32_t sbb = sb0 + B_BASE2 + (c & 1) * B_ST2;
#pragma unroll
        for (int s = 0; s < 2; s++) {
            const int ks = s * 16;
            uint32_t ah[2][4], al[2][4];
#pragma unroll
            for (int mt = 0; mt < 2; mt++) {
                uint32_t ro = SWZ64((uint32_t)((wm * 32 + mt * 16 + (lane & 15)) * 64 + (ks + (lane >> 4) * 8) * 2));
                ldmx4(ah[mt], sa + ro);
                ldmx4(al[mt], sa + 4096 + ro);
            }
            uint32_t bh[2][4], bl[2][4];
#pragma unroll
            for (int np = 0; np < 2; np++) {
                uint32_t ro = SWZ64((uint32_t)((wn * 32 + np * 16 + ((lane >> 4) & 1) * 8 + (lane & 7)) * 64 +
                                               (ks + ((lane >> 3) & 1) * 8) * 2));
                ldmx4(bh[np], sbb + ro);
                ldmx4(bl[np], sbb + 4096 + ro);
            }
#pragma unroll
            for (int mt = 0; mt < 2; mt++)
#pragma unroll
                for (int np = 0; np < 2; np++)
#pragma unroll
                    for (int h = 0; h < 2; h++) {
                        const int nt2 = np * 2 + h;
                        mma_bf16(acc[mt][nt2], ah[mt], &bh[np][h * 2]);
                        mma_bf16(acc[mt][nt2], ah[mt], &bl[np][h * 2]);
                        mma_bf16(acc[mt][nt2], al[mt], &bh[np][h * 2]);
                    }
        }
        if (c + 1 < NC2) {
            char* stc = smem + B_BASE2 + ((c + 1) & 1) * B_ST2;
            uint2 hp, lp;
#pragma unroll
            for (int j = 0; j < 4; j++) { split4(bR[j], hp, lp); *(uint2*)(stc + boff[j]) = hp; *(uint2*)(stc + 4096 + boff[j]) = lp; }
        }
    }

    // epilogue: weighted atomic combine
#pragma unroll
    for (int mt = 0; mt < 2; mt++) {
        const int lr0 = wm * 32 + mt * 16 + (lane >> 2);
        const int tok0 = s_tok[lr0];     const float wt0 = s_w[lr0];
        const int tok1 = s_tok[lr0 + 8]; const float wt1 = s_w[lr0 + 8];
#pragma unroll
        for (int nt2 = 0; nt2 < 4; nt2++) {
            const int col = n0 + wn * 32 + nt2 * 8 + 2 * (lane & 3);
            float* o0 = out + (size_t)tok0 * HDIM + col;
            float* o1 = out + (size_t)tok1 * HDIM + col;
            atomicAdd(o0,     wt0 * acc[mt][nt2][0]);
            atomicAdd(o0 + 1, wt0 * acc[mt][nt2][1]);
            atomicAdd(o1,     wt1 * acc[mt][nt2][2]);
            atomicAdd(o1 + 1, wt1 * acc[mt][nt2][3]);
        }
    }
}

// ---------------- launch ----------------
extern "C" void kernel_launch(void* const* d_in, const int* in_sizes, int n_in,
                              void* d_out, int out_size) {
    const float* x  = (const float*)d_in[0];
    const float* gw = (const float*)d_in[1];
    const float* w1 = (const float*)d_in[2];
    const float* w2 = (const float*)d_in[3];
    const float* w3 = (const float*)d_in[4];

    float* out    = (float*)d_out;
    float* logits = out + (size_t)TOK * HDIM;

    cudaFuncSetAttribute(moe_gemm13, cudaFuncAttributeMaxDynamicSharedMemorySize, SM13);
    cudaFuncSetAttribute(moe_gemm2,  cudaFuncAttributeMaxDynamicSharedMemorySize, SM2);

    router_kernel<<<TOK, 128>>>(x, gw, out, logits);
    build_lists<<<1, 256>>>();
    moe_gemm13<<<dim3(FDIM / 64, MAXTILES), 128, SM13>>>(w1, w3);
    moe_gemm2<<<dim3(HDIM / 64, MAXTILES), 128, SM2>>>(w2, out);
}